// round 14
// baseline (speedup 1.0000x reference)
#include <cuda_runtime.h>
#include <cuda_fp16.h>
#include <math.h>
#include <stdint.h>

#define Bsz 128
#define D 100
#define D2 10000
#define M_ROWS 12800      // B*D
#define M_PAD 12864       // 134 * 96
#define MTILE 96
#define KP 128            // padded K (storage in gmem scratch)
#define K_STEPS 7         // 7*16 = 112 >= 100
#define NTILE 64
#define NBLK 13           // i padded to 104 -> 13 blocks of 8
#define NPAIRS 91         // 13*14/2
#define N_SYM (NPAIRS * 64)   // 5824 packed hess columns
#define NJ_PAD 128        // 2 jac n-tiles
#define THREADS 256

#define NXT NPAIRS        // 91 hess n-tiles
#define NYT (M_PAD / MTILE)   // 134 m-tiles
#define TOT_TILES (NXT * NYT) // 12194
#define NCTA 296          // 2 per SM

// ---------------- scratch (device globals) ----------------
__device__ float g_G0[M_ROWS];
__device__ float g_G1[M_ROWS];
__device__ float g_G2[M_ROWS];
__device__ __half g_AJh[M_PAD * KP];                 // fp16 A (jac)
__device__ __half g_AHh[M_PAD * KP];                 // fp16 A (hess)
__device__ __half g_PBh[(size_t)N_SYM * KP];         // packed sym P (fp16)
__device__ __half g_BJh[NJ_PAD * KP];                // W1t (fp16)

// ---------------- helpers ----------------
__device__ __forceinline__ uint32_t smem_to_u32(const void* p) {
    uint32_t a;
    asm("{ .reg .u64 t; cvta.to.shared.u64 t, %1; cvt.u32.u64 %0, t; }" : "=r"(a) : "l"(p));
    return a;
}
__device__ __forceinline__ void ldm4(uint32_t r[4], uint32_t addr) {
    asm volatile("ldmatrix.sync.aligned.m8n8.x4.shared.b16 {%0,%1,%2,%3}, [%4];"
                 : "=r"(r[0]), "=r"(r[1]), "=r"(r[2]), "=r"(r[3]) : "r"(addr));
}
__device__ __forceinline__ void mma_f16(float c[4], const uint32_t a[4],
                                        uint32_t b0, uint32_t b1) {
    asm volatile(
        "mma.sync.aligned.m16n8k16.row.col.f32.f16.f16.f32 "
        "{%0,%1,%2,%3}, {%4,%5,%6,%7}, {%8,%9}, {%0,%1,%2,%3};"
        : "+f"(c[0]), "+f"(c[1]), "+f"(c[2]), "+f"(c[3])
        : "r"(a[0]), "r"(a[1]), "r"(a[2]), "r"(a[3]), "r"(b0), "r"(b1));
}
__device__ __forceinline__ void cp16(uint32_t dst, const void* src) {
    asm volatile("cp.async.cg.shared.global [%0], [%1], 16;" :: "r"(dst), "l"(src) : "memory");
}
__device__ __forceinline__ void decode_pair(int t, int& bi, int& bj) {
    int b = 0, rem = t;
    while (rem >= NBLK - b) { rem -= NBLK - b; b++; }
    bi = b; bj = b + rem;
}

// ---------------- prep: z, gelu derivatives ----------------
__global__ void prep_kernel(const float* __restrict__ x,
                            const float* __restrict__ W1,
                            const float* __restrict__ b1) {
    int b = blockIdx.x;
    __shared__ float xs[D];
    int t = threadIdx.x;
    if (t < D) xs[t] = x[b * D + t];
    __syncthreads();
    if (t < D) {
        const float* w = W1 + t * D;
        float z = b1[t];
        #pragma unroll 4
        for (int i = 0; i < D; i++) z = fmaf(w[i], xs[i], z);
        float cdf = 0.5f * (1.0f + erff(z * 0.70710678118654752f));
        float pdf = 0.39894228040143268f * expf(-0.5f * z * z);
        g_G0[b * D + t] = z * cdf;
        g_G1[b * D + t] = cdf + z * pdf;
        g_G2[b * D + t] = (2.0f - z * z) * pdf;
    }
}

__global__ void out_kernel(const float* __restrict__ W2,
                           const float* __restrict__ b2,
                           float* __restrict__ out) {
    int b = blockIdx.x;
    __shared__ float gs[D];
    int t = threadIdx.x;
    if (t < D) gs[t] = g_G0[b * D + t];
    __syncthreads();
    if (t < D) {
        const float* w = W2 + t * D;
        float acc = b2[t];
        #pragma unroll 4
        for (int k = 0; k < D; k++) acc = fmaf(w[k], gs[k], acc);
        out[b * D + t] = acc;
    }
}

// ---------------- A matrices (fp16; padded rows -> 0) ----------------
__global__ void buildA_kernel(const float* __restrict__ W2) {
    int m = blockIdx.x;          // 0..M_PAD-1
    int k = threadIdx.x;         // 128
    float aj = 0.0f, ah = 0.0f;
    if (m < M_ROWS && k < D) {
        int b = m / D, o = m % D;
        float w = W2[o * D + k];
        aj = w * g_G1[b * D + k];
        ah = w * g_G2[b * D + k];
    }
    g_AJh[m * KP + k] = __float2half_rn(aj);
    g_AHh[m * KP + k] = __float2half_rn(ah);
}

// ---------------- packed symmetric P + BJ (fp16, one launch) ----------------
__global__ void buildPBJ_kernel(const float* __restrict__ W1) {
    int n = blockIdx.x;   // 0..N_SYM+NJ_PAD-1
    int k = threadIdx.x;  // 128
    if (n < N_SYM) {
        int t = n >> 6, nl = n & 63;
        int bi, bj; decode_pair(t, bi, bj);
        int i = bi * 8 + (nl >> 3);
        int j = bj * 8 + (nl & 7);
        float v = 0.0f;
        if (i < D && j < D && k < D)
            v = __ldg(W1 + k * D + i) * __ldg(W1 + k * D + j);
        g_PBh[(size_t)n * KP + k] = __float2half_rn(v);
    } else {
        int nn = n - N_SYM;     // 0..127
        float v = (nn < D && k < D) ? W1[k * D + nn] : 0.0f;
        g_BJh[nn * KP + k] = __float2half_rn(v);
    }
}

// ---------------- GEMM common pieces ----------------
#define PITCH 240                          // bytes per smem row (112 fp16 + pad)
#define CHUNKS 14
#define A_TILE_BYTES (MTILE * PITCH)       // 23040
#define B_TILE_BYTES (NTILE * PITCH)       // 15360
#define CS_BYTES (MTILE * 68 * 4)          // 26112
#define CPITCH 68
// hess persistent smem: A x2, B x2, Cs
#define H_SMEM (2 * A_TILE_BYTES + 2 * B_TILE_BYTES + CS_BYTES)  // 102912
// jac one-shot smem
#define J_SMEM (A_TILE_BYTES + B_TILE_BYTES + CS_BYTES)          // 64512

template <int ROWS>
__device__ __forceinline__ void load_tile(uint32_t dst, const __half* __restrict__ src,
                                          int row0, int tid) {
    constexpr int TOT = ROWS * CHUNKS;
    #pragma unroll
    for (int it = 0; it < (TOT + THREADS - 1) / THREADS; it++) {
        int e = tid + it * THREADS;
        if (TOT % THREADS != 0 && e >= TOT) break;
        int row = e / CHUNKS, col = e % CHUNKS;
        cp16(dst + row * PITCH + col * 16,
             src + (size_t)(row0 + row) * KP + col * 8);
    }
}

// mainloop: 8 warps (2m x 4n), warp tile 48x16, single fp16
__device__ __forceinline__ void run_mainloop(uint32_t uA, uint32_t uB,
                                             float acc[3][2][4], int lane, int wid) {
    int wm = (wid & 1) * 48;
    int wn = (wid >> 1) * 16;
    int tt = lane >> 3, rr = lane & 7;
    uint32_t aoff = (uint32_t)((wm + (tt & 1) * 8 + rr) * PITCH + (tt >> 1) * 16);
    uint32_t boff = (uint32_t)((wn + (tt >> 1) * 8 + rr) * PITCH + (tt & 1) * 16);
    #pragma unroll
    for (int ks = 0; ks < K_STEPS; ks++) {
        uint32_t kb = ks * 32;
        uint32_t ah[3][4], bh[4];
        #pragma unroll
        for (int mf = 0; mf < 3; mf++) ldm4(ah[mf], uA + aoff + mf * 16 * PITCH + kb);
        ldm4(bh, uB + boff + kb);
        #pragma unroll
        for (int mf = 0; mf < 3; mf++)
            #pragma unroll
            for (int nf = 0; nf < 2; nf++)
                mma_f16(acc[mf][nf], ah[mf], bh[nf * 2], bh[nf * 2 + 1]);
    }
}

__device__ __forceinline__ void stage_C(float* Cs, float acc[3][2][4], int lane, int wid) {
    int wm = (wid & 1) * 48;
    int wn = (wid >> 1) * 16;
    #pragma unroll
    for (int mf = 0; mf < 3; mf++) {
        int mrow = wm + mf * 16 + (lane >> 2);
        #pragma unroll
        for (int nf = 0; nf < 2; nf++) {
            int ncol = wn + nf * 8 + 2 * (lane & 3);
            Cs[mrow * CPITCH + ncol]           = acc[mf][nf][0];
            Cs[mrow * CPITCH + ncol + 1]       = acc[mf][nf][1];
            Cs[(mrow + 8) * CPITCH + ncol]     = acc[mf][nf][2];
            Cs[(mrow + 8) * CPITCH + ncol + 1] = acc[mf][nf][3];
        }
    }
}

// ---------------- hess: persistent, A-resident strip, B double-buffered ----------------
__global__ void __launch_bounds__(THREADS, 2)
hess_gemm_kernel(float* __restrict__ Chess) {
    extern __shared__ char smem[];
    uint32_t uA0 = smem_to_u32(smem);
    uint32_t uA1 = uA0 + A_TILE_BYTES;
    uint32_t uB0 = uA1 + A_TILE_BYTES;
    uint32_t uB1 = uB0 + B_TILE_BYTES;
    float* Cs = reinterpret_cast<float*>(smem + 2 * A_TILE_BYTES + 2 * B_TILE_BYTES);

    int tid = threadIdx.x;
    int lane = tid & 31, wid = tid >> 5;

    int c = blockIdx.x;
    const int q = TOT_TILES / NCTA;     // 41
    const int r = TOT_TILES % NCTA;     // 58
    int t0 = c * q + (c < r ? c : r);
    int t1 = t0 + q + (c < r ? 1 : 0);

    int by0 = t0 / NXT;
    int tch = (by0 + 1) * NXT;          // first tile with by0+1 (<= one change per strip)

    // prologue: loads for tile t0
    load_tile<MTILE>(uA0, g_AHh, by0 * MTILE, tid);
    load_tile<NTILE>(uB0, g_PBh, (t0 - by0 * NXT) * NTILE, tid);
    asm volatile("cp.async.commit_group;" ::: "memory");

    for (int t = t0; t < t1; t++) {
        int p = (t - t0) & 1;
        if (t + 1 < t1) {
            int by1 = (t + 1 >= tch) ? by0 + 1 : by0;
            int bx1 = (t + 1) - by1 * NXT;
            if (t + 1 == tch)
                load_tile<MTILE>(uA1, g_AHh, by1 * MTILE, tid);
            load_tile<NTILE>(p ? uB0 : uB1, g_PBh, bx1 * NTILE, tid);
            asm volatile("cp.async.commit_group;" ::: "memory");
            asm volatile("cp.async.wait_group 1;" ::: "memory");
        } else {
            asm volatile("cp.async.wait_group 0;" ::: "memory");
        }
        __syncthreads();

        int by = (t >= tch) ? by0 + 1 : by0;
        int bx = t - by * NXT;
        int m0 = by * MTILE;
        uint32_t uA = (t >= tch) ? uA1 : uA0;
        uint32_t uB = p ? uB1 : uB0;

        float acc[3][2][4];
        #pragma unroll
        for (int i = 0; i < 3; i++)
            #pragma unroll
            for (int j = 0; j < 2; j++)
                #pragma unroll
                for (int e = 0; e < 4; e++) acc[i][j][e] = 0.0f;

        run_mainloop(uA, uB, acc, lane, wid);

        __syncthreads();
        stage_C(Cs, acc, lane, wid);
        __syncthreads();

        int bi, bj; decode_pair(bx, bi, bj);
        if (bi < 12 && bj < 12) {
            // primary (i,j): float4 stores, only m-guard
            #pragma unroll
            for (int it = 0; it < MTILE * 16 / THREADS; it++) {
                int e = tid + it * THREADS;
                int m = e >> 4, qq = e & 15;
                int gm = m0 + m;
                if (gm >= M_ROWS) continue;
                int i = bi * 8 + (qq >> 1);
                int jb = bj * 8 + (qq & 1) * 4;
                float4 v = *reinterpret_cast<const float4*>(&Cs[m * CPITCH + qq * 4]);
                *reinterpret_cast<float4*>(&Chess[(size_t)gm * D2 + i * D + jb]) = v;
            }
            // mirror (j,i)
            #pragma unroll
            for (int it = 0; it < MTILE * 16 / THREADS; it++) {
                int e = tid + it * THREADS;
                int m = e >> 4, qq = e & 15;
                int gm = m0 + m;
                if (gm >= M_ROWS) continue;
                int lj = qq >> 1, li4 = (qq & 1) * 4;
                int jrow = bj * 8 + lj;
                int ib = bi * 8 + li4;
                float4 v;
                v.x = Cs[m * CPITCH + (li4 + 0) * 8 + lj];
                v.y = Cs[m * CPITCH + (li4 + 1) * 8 + lj];
                v.z = Cs[m * CPITCH + (li4 + 2) * 8 + lj];
                v.w = Cs[m * CPITCH + (li4 + 3) * 8 + lj];
                *reinterpret_cast<float4*>(&Chess[(size_t)gm * D2 + jrow * D + ib]) = v;
            }
        } else {
            // edge tiles: scalar guarded
            #pragma unroll
            for (int it = 0; it < MTILE * 64 / THREADS; it++) {
                int e = tid + it * THREADS;
                int m = e >> 6, nl = e & 63;
                int gm = m0 + m;
                int i = bi * 8 + (nl >> 3), j = bj * 8 + (nl & 7);
                if (i < D && j < D && gm < M_ROWS)
                    Chess[(size_t)gm * D2 + i * D + j] = Cs[m * CPITCH + nl];
            }
            #pragma unroll
            for (int it = 0; it < MTILE * 64 / THREADS; it++) {
                int e = tid + it * THREADS;
                int m = e >> 6, nl = e & 63;
                int gm = m0 + m;
                int lj = nl >> 3, li = nl & 7;
                int i = bi * 8 + li, j = bj * 8 + lj;
                if (i < D && j < D && gm < M_ROWS)
                    Chess[(size_t)gm * D2 + j * D + i] = Cs[m * CPITCH + li * 8 + lj];
            }
        }
        __syncthreads();   // protect Cs + B buffer reuse next iteration
    }
}

// ---------------- jac: small one-shot GEMM ----------------
__global__ void __launch_bounds__(THREADS, 2)
jac_gemm_kernel(float* __restrict__ Cjac) {
    extern __shared__ char smem[];
    uint32_t uA = smem_to_u32(smem);
    uint32_t uB = uA + A_TILE_BYTES;
    float* Cs = reinterpret_cast<float*>(smem + A_TILE_BYTES + B_TILE_BYTES);

    int tid = threadIdx.x;
    int lane = tid & 31, wid = tid >> 5;
    int n0 = blockIdx.x * NTILE;
    int m0 = blockIdx.y * MTILE;

    load_tile<MTILE>(uA, g_AJh, m0, tid);
    load_tile<NTILE>(uB, g_BJh, n0, tid);
    asm volatile("cp.async.commit_group;" ::: "memory");
    asm volatile("cp.async.wait_group 0;" ::: "memory");
    __syncthreads();

    float acc[3][2][4];
    #pragma unroll
    for (int i = 0; i < 3; i++)
        #pragma unroll
        for (int j = 0; j < 2; j++)
            #pragma unroll
            for (int e = 0; e < 4; e++) acc[i][j][e] = 0.0f;

    run_mainloop(uA, uB, acc, lane, wid);

    __syncthreads();
    stage_C(Cs, acc, lane, wid);
    __syncthreads();

    #pragma unroll
    for (int it = 0; it < MTILE * 64 / THREADS; it++) {
        int e = tid + it * THREADS;
        int m = e >> 6, nl = e & 63;
        int n = n0 + nl;
        int gm = m0 + m;
        if (n < D && gm < M_ROWS) Cjac[(size_t)gm * D + n] = Cs[m * CPITCH + nl];
    }
}

// ---------------- host ----------------
extern "C" void kernel_launch(void* const* d_in, const int* in_sizes, int n_in,
                              void* d_out, int out_size) {
    const float* x  = (const float*)d_in[0];
    const float* W1 = (const float*)d_in[1];
    const float* b1 = (const float*)d_in[2];
    const float* W2 = (const float*)d_in[3];
    const float* b2 = (const float*)d_in[4];

    float* out  = (float*)d_out;
    float* jac  = out + Bsz * D;
    float* hess = jac + (size_t)Bsz * D * D;

    cudaFuncSetAttribute(hess_gemm_kernel, cudaFuncAttributeMaxDynamicSharedMemorySize, H_SMEM);
    cudaFuncSetAttribute(jac_gemm_kernel,  cudaFuncAttributeMaxDynamicSharedMemorySize, J_SMEM);

    buildPBJ_kernel<<<N_SYM + NJ_PAD, 128>>>(W1);     // 0 (needs only W1)
    prep_kernel<<<Bsz, 128>>>(x, W1, b1);             // 1
    buildA_kernel<<<M_PAD, 128>>>(W2);                // 2 (needs prep)
    hess_gemm_kernel<<<NCTA, THREADS, H_SMEM>>>(hess);          // 3 <- profiled
    {
        dim3 grid(NJ_PAD / NTILE, NYT);
        jac_gemm_kernel<<<grid, THREADS, J_SMEM>>>(jac);        // 4
    }
    out_kernel<<<Bsz, 128>>>(W2, b2, out);            // 5
}

// round 15
// speedup vs baseline: 2.2395x; 2.2395x over previous
#include <cuda_runtime.h>
#include <cuda_fp16.h>
#include <math.h>
#include <stdint.h>

#define Bsz 128
#define D 100
#define D2 10000
#define M_ROWS 12800      // B*D
#define M_PAD 12864       // 134 * 96
#define MTILE 96
#define KP 128            // padded K (storage in gmem scratch)
#define K_STEPS 7         // 7*16 = 112 >= 100
#define NTILE 64
#define NBLK 13           // i padded to 104 -> 13 blocks of 8
#define NPAIRS 91         // 13*14/2
#define N_SYM (NPAIRS * 64)   // 5824 packed hess columns
#define NJ_PAD 128        // 2 jac n-tiles
#define THREADS 128

// ---------------- scratch (device globals) ----------------
__device__ __half g_AJh[M_PAD * KP];                 // fp16 A (jac)
__device__ __half g_AHh[M_PAD * KP];                 // fp16 A (hess)
__device__ __half g_PBh[(size_t)N_SYM * KP];         // packed sym P, high
__device__ __half g_PBl[(size_t)N_SYM * KP];         // packed sym P, low
__device__ __half g_BJh[NJ_PAD * KP];                // W1t, high
__device__ __half g_BJl[NJ_PAD * KP];                // W1t, low

// ---------------- helpers ----------------
__device__ __forceinline__ uint32_t smem_to_u32(const void* p) {
    uint32_t a;
    asm("{ .reg .u64 t; cvta.to.shared.u64 t, %1; cvt.u32.u64 %0, t; }" : "=r"(a) : "l"(p));
    return a;
}
__device__ __forceinline__ void split_f16(float v, __half& h, __half& l) {
    h = __float2half_rn(v);
    l = __float2half_rn(v - __half2float(h));
}
__device__ __forceinline__ void ldm4(uint32_t r[4], uint32_t addr) {
    asm volatile("ldmatrix.sync.aligned.m8n8.x4.shared.b16 {%0,%1,%2,%3}, [%4];"
                 : "=r"(r[0]), "=r"(r[1]), "=r"(r[2]), "=r"(r[3]) : "r"(addr));
}
__device__ __forceinline__ void mma_f16(float c[4], const uint32_t a[4],
                                        uint32_t b0, uint32_t b1) {
    asm volatile(
        "mma.sync.aligned.m16n8k16.row.col.f32.f16.f16.f32 "
        "{%0,%1,%2,%3}, {%4,%5,%6,%7}, {%8,%9}, {%0,%1,%2,%3};"
        : "+f"(c[0]), "+f"(c[1]), "+f"(c[2]), "+f"(c[3])
        : "r"(a[0]), "r"(a[1]), "r"(a[2]), "r"(a[3]), "r"(b0), "r"(b1));
}
__device__ __forceinline__ void cp16(uint32_t dst, const void* src) {
    asm volatile("cp.async.cg.shared.global [%0], [%1], 16;" :: "r"(dst), "l"(src) : "memory");
}
__device__ __forceinline__ void decode_pair(int t, int& bi, int& bj) {
    int b = 0, rem = t;
    while (rem >= NBLK - b) { rem -= NBLK - b; b++; }
    bi = b; bj = b + rem;
}

// ---------------- fused prep: GELU derivs + out row + A rows for one batch b ----------------
// grid: Bsz+1 blocks of 128. Block Bsz zeroes the padded A rows [12800, 12864).
__global__ void fused_prep_kernel(const float* __restrict__ x,
                                  const float* __restrict__ W1,
                                  const float* __restrict__ b1,
                                  const float* __restrict__ W2,
                                  const float* __restrict__ b2,
                                  float* __restrict__ out) {
    int b = blockIdx.x;
    int t = threadIdx.x;

    if (b == Bsz) {
        // zero A padding rows
        for (int m = M_ROWS; m < M_PAD; m++) {
            g_AJh[m * KP + t] = __float2half_rn(0.0f);
            g_AHh[m * KP + t] = __float2half_rn(0.0f);
        }
        return;
    }

    __shared__ float xs[D];
    __shared__ float G0s[D], G1s[D], G2s[D];
    if (t < D) xs[t] = x[b * D + t];
    __syncthreads();
    if (t < D) {
        const float* w = W1 + t * D;
        float z = b1[t];
        #pragma unroll 4
        for (int i = 0; i < D; i++) z = fmaf(w[i], xs[i], z);
        float cdf = 0.5f * (1.0f + erff(z * 0.70710678118654752f));
        float pdf = 0.39894228040143268f * expf(-0.5f * z * z);
        G0s[t] = z * cdf;
        G1s[t] = cdf + z * pdf;
        G2s[t] = (2.0f - z * z) * pdf;
    }
    __syncthreads();

    // out row
    if (t < D) {
        const float* w = W2 + t * D;
        float acc = b2[t];
        #pragma unroll 4
        for (int k = 0; k < D; k++) acc = fmaf(w[k], G0s[k], acc);
        out[b * D + t] = acc;
    }

    // A rows: m = b*100 + o, k = t
    float g1 = (t < D) ? G1s[t] : 0.0f;
    float g2 = (t < D) ? G2s[t] : 0.0f;
    for (int o = 0; o < D; o++) {
        float w = (t < D) ? W2[o * D + t] : 0.0f;
        size_t m = (size_t)(b * D + o) * KP + t;
        g_AJh[m] = __float2half_rn(w * g1);
        g_AHh[m] = __float2half_rn(w * g2);
    }
}

// ---------------- packed symmetric P + BJ, fp16 split (one launch) ----------------
__global__ void buildPBJ_kernel(const float* __restrict__ W1) {
    int n = blockIdx.x;   // 0..N_SYM+NJ_PAD-1
    int k = threadIdx.x;  // 128
    if (n < N_SYM) {
        int t = n >> 6, nl = n & 63;
        int bi, bj; decode_pair(t, bi, bj);
        int i = bi * 8 + (nl >> 3);
        int j = bj * 8 + (nl & 7);
        float v = 0.0f;
        if (i < D && j < D && k < D)
            v = __ldg(W1 + k * D + i) * __ldg(W1 + k * D + j);
        __half h, l;
        split_f16(v, h, l);
        g_PBh[(size_t)n * KP + k] = h;
        g_PBl[(size_t)n * KP + k] = l;
    } else {
        int nn = n - N_SYM;     // 0..127
        float v = (nn < D && k < D) ? W1[k * D + nn] : 0.0f;
        __half h, l;
        split_f16(v, h, l);
        g_BJh[nn * KP + k] = h;
        g_BJl[nn * KP + k] = l;
    }
}

// ---------------- HMMA GEMM: 96x64 CTA tile, 4 warps (2m x 2n), fp16 2-term ----------------
// blockIdx.x < NPAIRS: hess pair tile; else jac n-tile (bx - NPAIRS)
#define PITCH 240                          // bytes per smem row (112 fp16 + pad)
#define CHUNKS 14
#define A_TILE_BYTES (MTILE * PITCH)       // 23040
#define B_TILE_BYTES (NTILE * PITCH)       // 15360
#define SMEM_BYTES (A_TILE_BYTES + 2 * B_TILE_BYTES)  // 53760 -> 4 CTAs/SM
#define CPITCH 68                          // C staging pitch (floats)

template <int ROWS>
__device__ __forceinline__ void load_tile_async(uint32_t dst, const __half* __restrict__ src,
                                                int row0, int tid) {
    constexpr int TOT = ROWS * CHUNKS;
    #pragma unroll
    for (int it = 0; it < (TOT + THREADS - 1) / THREADS; it++) {
        int c = tid + it * THREADS;
        if (TOT % THREADS != 0 && c >= TOT) break;
        int row = c / CHUNKS, col = c % CHUNKS;
        cp16(dst + row * PITCH + col * 16,
             src + (size_t)(row0 + row) * KP + col * 8);
    }
}

__global__ void __launch_bounds__(THREADS, 4)
mma_gemm_kernel(float* __restrict__ Chess, float* __restrict__ Cjac) {
    int bx = blockIdx.x;
    bool is_jac = bx >= NPAIRS;

    const __half* __restrict__ Ah = is_jac ? g_AJh : g_AHh;
    const __half* __restrict__ Bh = is_jac ? g_BJh : g_PBh;
    const __half* __restrict__ Bl = is_jac ? g_BJl : g_PBl;
    int n0 = is_jac ? (bx - NPAIRS) * NTILE : bx * NTILE;

    extern __shared__ char smem[];
    uint32_t uAh = smem_to_u32(smem);
    uint32_t uBh = uAh + A_TILE_BYTES;
    uint32_t uBl = uBh + B_TILE_BYTES;

    int tid = threadIdx.x;
    int m0 = blockIdx.y * MTILE;

    load_tile_async<MTILE>(uAh, Ah, m0, tid);
    load_tile_async<NTILE>(uBh, Bh, n0, tid);
    load_tile_async<NTILE>(uBl, Bl, n0, tid);
    asm volatile("cp.async.commit_group;" ::: "memory");
    asm volatile("cp.async.wait_group 0;" ::: "memory");
    __syncthreads();

    int lane = tid & 31, wid = tid >> 5;
    int wm = (wid & 1) * 48;      // 2 m-warps x 48
    int wn = (wid >> 1) * 32;     // 2 n-warps x 32
    int t = lane >> 3, r = lane & 7;

    uint32_t aoff = (uint32_t)((wm + (t & 1) * 8 + r) * PITCH + (t >> 1) * 16);
    uint32_t boff = (uint32_t)((wn + (t >> 1) * 8 + r) * PITCH + (t & 1) * 16);

    float acc[3][4][4];
    #pragma unroll
    for (int i = 0; i < 3; i++)
        #pragma unroll
        for (int j = 0; j < 4; j++)
            #pragma unroll
            for (int e = 0; e < 4; e++) acc[i][j][e] = 0.0f;

    #pragma unroll
    for (int ks = 0; ks < K_STEPS; ks++) {
        uint32_t kb = ks * 32;
        uint32_t ah[3][4], bh[8], bl[8];
        #pragma unroll
        for (int mf = 0; mf < 3; mf++) ldm4(ah[mf], uAh + aoff + mf * 16 * PITCH + kb);
        ldm4(bh,     uBh + boff + kb);
        ldm4(bh + 4, uBh + boff + 16 * PITCH + kb);
        #pragma unroll
        for (int mf = 0; mf < 3; mf++)
            #pragma unroll
            for (int nf = 0; nf < 4; nf++)
                mma_f16(acc[mf][nf], ah[mf], bh[nf * 2], bh[nf * 2 + 1]);

        ldm4(bl,     uBl + boff + kb);
        ldm4(bl + 4, uBl + boff + 16 * PITCH + kb);
        #pragma unroll
        for (int mf = 0; mf < 3; mf++)
            #pragma unroll
            for (int nf = 0; nf < 4; nf++)
                mma_f16(acc[mf][nf], ah[mf], bl[nf * 2], bl[nf * 2 + 1]);
    }

    // ---- stage C tile in smem (96*68*4 = 26112 <= 53760) ----
    __syncthreads();
    float* Cs = reinterpret_cast<float*>(smem);
    #pragma unroll
    for (int mf = 0; mf < 3; mf++) {
        int mrow = wm + mf * 16 + (lane >> 2);
        #pragma unroll
        for (int nf = 0; nf < 4; nf++) {
            int ncol = wn + nf * 8 + 2 * (lane & 3);
            *reinterpret_cast<float2*>(&Cs[mrow * CPITCH + ncol]) =
                make_float2(acc[mf][nf][0], acc[mf][nf][1]);
            *reinterpret_cast<float2*>(&Cs[(mrow + 8) * CPITCH + ncol]) =
                make_float2(acc[mf][nf][2], acc[mf][nf][3]);
        }
    }
    __syncthreads();

    if (is_jac) {
        // jac: guarded scalar writes
        #pragma unroll
        for (int it = 0; it < MTILE * 64 / THREADS; it++) {
            int e = tid + it * THREADS;
            int m = e >> 6, nl = e & 63;
            int n = n0 + nl;
            int gm = m0 + m;
            if (n < D && gm < M_ROWS) Cjac[(size_t)gm * D + n] = Cs[m * CPITCH + nl];
        }
    } else {
        int bi, bj; decode_pair(bx, bi, bj);
        if (bi < 12 && bj < 12) {
            // fast path: float4 stores, only m-guard
            #pragma unroll
            for (int it = 0; it < MTILE * 16 / THREADS; it++) {
                int e = tid + it * THREADS;
                int m = e >> 4, q = e & 15;
                int gm = m0 + m;
                if (gm >= M_ROWS) continue;
                int i = bi * 8 + (q >> 1);
                int jb = bj * 8 + (q & 1) * 4;
                float4 v = *reinterpret_cast<const float4*>(&Cs[m * CPITCH + q * 4]);
                *reinterpret_cast<float4*>(&Chess[(size_t)gm * D2 + i * D + jb]) = v;
            }
            #pragma unroll
            for (int it = 0; it < MTILE * 16 / THREADS; it++) {
                int e = tid + it * THREADS;
                int m = e >> 4, q = e & 15;
                int gm = m0 + m;
                if (gm >= M_ROWS) continue;
                int lj = q >> 1, li4 = (q & 1) * 4;
                int jrow = bj * 8 + lj;
                int ib = bi * 8 + li4;
                float4 v;
                v.x = Cs[m * CPITCH + (li4 + 0) * 8 + lj];
                v.y = Cs[m * CPITCH + (li4 + 1) * 8 + lj];
                v.z = Cs[m * CPITCH + (li4 + 2) * 8 + lj];
                v.w = Cs[m * CPITCH + (li4 + 3) * 8 + lj];
                *reinterpret_cast<float4*>(&Chess[(size_t)gm * D2 + jrow * D + ib]) = v;
            }
        } else {
            // edge tiles: scalar guarded
            #pragma unroll
            for (int it = 0; it < MTILE * 64 / THREADS; it++) {
                int e = tid + it * THREADS;
                int m = e >> 6, nl = e & 63;
                int gm = m0 + m;
                int i = bi * 8 + (nl >> 3), j = bj * 8 + (nl & 7);
                if (i < D && j < D && gm < M_ROWS)
                    Chess[(size_t)gm * D2 + i * D + j] = Cs[m * CPITCH + nl];
            }
            #pragma unroll
            for (int it = 0; it < MTILE * 64 / THREADS; it++) {
                int e = tid + it * THREADS;
                int m = e >> 6, nl = e & 63;
                int gm = m0 + m;
                int lj = nl >> 3, li = nl & 7;
                int i = bi * 8 + li, j = bj * 8 + lj;
                if (i < D && j < D && gm < M_ROWS)
                    Chess[(size_t)gm * D2 + j * D + i] = Cs[m * CPITCH + li * 8 + lj];
            }
        }
    }
}

// ---------------- host ----------------
extern "C" void kernel_launch(void* const* d_in, const int* in_sizes, int n_in,
                              void* d_out, int out_size) {
    const float* x  = (const float*)d_in[0];
    const float* W1 = (const float*)d_in[1];
    const float* b1 = (const float*)d_in[2];
    const float* W2 = (const float*)d_in[3];
    const float* b2 = (const float*)d_in[4];

    float* out  = (float*)d_out;
    float* jac  = out + Bsz * D;
    float* hess = jac + (size_t)Bsz * D * D;

    cudaFuncSetAttribute(mma_gemm_kernel, cudaFuncAttributeMaxDynamicSharedMemorySize, SMEM_BYTES);

    buildPBJ_kernel<<<N_SYM + NJ_PAD, 128>>>(W1);                          // 0
    fused_prep_kernel<<<Bsz + 1, 128>>>(x, W1, b1, W2, b2, out);           // 1
    {
        dim3 grid(NPAIRS + 2, M_PAD / MTILE);
        mma_gemm_kernel<<<grid, THREADS, SMEM_BYTES>>>(hess, jac);         // 2
    }
}